// round 8
// baseline (speedup 1.0000x reference)
#include <cuda_runtime.h>
#include <cstdint>

#define T_LEN   32768
#define NROWS   1024
#define IT      16                      // items per lane per chunk
#define CELEMS  (32 * IT)               // 512 elements per chunk
#define NCHUNK  (T_LEN / CELEMS)        // 64 chunks per row
#define STAGES  6
#define F4C     128                     // float4 per tensor per chunk
#define STAGE_F4 (2 * F4C)              // P + Q per stage
#define SMEM_F4  (STAGES * STAGE_F4)    // 1536 float4 = 24 KB

__device__ double g_partial[NROWS];
__device__ unsigned int g_count;

__device__ __forceinline__ void cp16(uint32_t dst, const float4* src) {
    asm volatile("cp.async.cg.shared.global [%0], [%1], 16;" :: "r"(dst), "l"(src));
}
__device__ __forceinline__ void cp_commit() {
    asm volatile("cp.async.commit_group;" ::: "memory");
}
template <int N>
__device__ __forceinline__ void cp_wait() {
    asm volatile("cp.async.wait_group %0;" :: "n"(N) : "memory");
}
__device__ __forceinline__ int swz(int v) { return v ^ ((v >> 3) & 7); }

__global__ void __launch_bounds__(32, 8)
wass_kernel(const float* __restrict__ yp, const float* __restrict__ yt,
            float* __restrict__ out) {
    __shared__ float4 smem[SMEM_F4];
    __shared__ bool is_last;

    const int lane = threadIdx.x;
    const int row  = blockIdx.x;

    const float4* __restrict__ p4 = (const float4*)(yp + (long)row * T_LEN);
    const float4* __restrict__ t4 = (const float4*)(yt + (long)row * T_LEN);
    const uint32_t sbase = (uint32_t)__cvta_generic_to_shared(smem);

    // Issue one stage (one commit group): 4 float4 per tensor per lane.
    auto issue = [&](int stage, int chunk) {
        const int vbase = chunk * F4C;
        #pragma unroll
        for (int i = 0; i < 4; i++) {
            int v  = i * 32 + lane;
            int sw = swz(v);
            cp16(sbase + (uint32_t)(stage * STAGE_F4 + sw) * 16u,       p4 + vbase + v);
            cp16(sbase + (uint32_t)(stage * STAGE_F4 + F4C + sw) * 16u, t4 + vbase + v);
        }
        cp_commit();
    };

    // Prologue: chunks 0..4 into stages 0..4 (5 groups pending).
    issue(0, 0); issue(1, 1); issue(2, 2); issue(3, 3); issue(4, 4);

    double dacc = 0.0;
    float  carry = 0.0f;

    // Consume 2 chunks per wait. 6 stages / step 2 -> stage pattern repeats every 3 iters.
    for (int f = 0; f < NCHUNK; f += 2) {
        cp_wait<3>();          // chunks f and f+1 complete (<=3 groups pending)
        __syncwarp();

        // Refill: chunks f+5, f+6 (2 commit groups; empty at tail to keep counts exact).
        {
            int n0 = f + 5, n1 = f + 6;
            if (n0 < NCHUNK) issue((f + 5) % STAGES, n0); else cp_commit();
            if (n1 < NCHUNK) issue((f + 6) % STAGES, n1); else cp_commit();
        }

        #pragma unroll
        for (int h = 0; h < 2; h++) {
            const int fc = f + h;
            const int s  = fc % STAGES;

            // Consume stage s: lane reads 16 contiguous elements (4 float4).
            float d[IT];
            #pragma unroll
            for (int j = 0; j < 4; j++) {
                int v  = lane * 4 + j;
                int sw = swz(v);
                float4 Pj = smem[s * STAGE_F4 + sw];
                float4 Qj = smem[s * STAGE_F4 + F4C + sw];
                d[4*j+0] = Pj.x - Qj.x;
                d[4*j+1] = Pj.y - Qj.y;
                d[4*j+2] = Pj.z - Qj.z;
                d[4*j+3] = Pj.w - Qj.w;
            }

            // Per-lane inclusive prefix + segment total.
            float pr[IT];
            pr[0] = d[0];
            #pragma unroll
            for (int k = 1; k < IT; k++) pr[k] = pr[k-1] + d[k];
            float seg = pr[IT-1];

            // Warp inclusive scan of segment sums.
            float inc = seg;
            #pragma unroll
            for (int o = 1; o < 32; o <<= 1) {
                float y = __shfl_up_sync(0xffffffffu, inc, o);
                if (lane >= o) inc += y;
            }
            float total = __shfl_sync(0xffffffffu, inc, 31);

            float base = carry + (inc - seg);
            carry += total;

            // Weighted |cumsum| accumulation, 2 independent FMA chains.
            const int idx0 = fc * CELEMS + lane * IT;
            const float w0 = (float)(T_LEN - idx0);
            float acc0 = 0.0f, acc1 = 0.0f;
            #pragma unroll
            for (int k = 0; k < IT; k += 2) {
                float r0 = base + pr[k];
                float r1 = base + pr[k+1];
                acc0 = fmaf(fabsf(r0), w0 - (float)k,       acc0);
                acc1 = fmaf(fabsf(r1), w0 - (float)(k + 1), acc1);
            }
            dacc += (double)(acc0 + acc1);
        }
    }

    // Warp reduction of dacc (deterministic).
    #pragma unroll
    for (int o = 16; o > 0; o >>= 1)
        dacc += __shfl_down_sync(0xffffffffu, dacc, o);
    if (lane == 0) {
        g_partial[row] = dacc;
        __threadfence();
        unsigned int prev = atomicAdd(&g_count, 1u);
        is_last = (prev == (unsigned int)(gridDim.x - 1));
    }
    __syncwarp();
    int last = __shfl_sync(0xffffffffu, (int)is_last, 0);

    // Last block: final deterministic reduce of 1024 partials with one warp.
    if (last) {
        if (lane == 0) g_count = 0;   // reset for graph replay
        double v = 0.0;
        #pragma unroll
        for (int j = 0; j < NROWS / 32; j++)
            v += g_partial[lane * (NROWS / 32) + j];
        #pragma unroll
        for (int o = 16; o > 0; o >>= 1)
            v += __shfl_down_sync(0xffffffffu, v, o);
        if (lane == 0) {
            double tc = (double)T_LEN * 16.0;            // T*C
            double scale = 2.0 / (tc * (tc + 1.0));
            out[0] = (float)((v / 64.0) * scale);        // mean over B=64
        }
    }
}

extern "C" void kernel_launch(void* const* d_in, const int* in_sizes, int n_in,
                              void* d_out, int out_size) {
    (void)in_sizes; (void)n_in; (void)out_size;
    const float* y_pred = (const float*)d_in[0];
    const float* y_true = (const float*)d_in[1];
    float* out = (float*)d_out;
    wass_kernel<<<NROWS, 32>>>(y_pred, y_true, out);
}